// round 3
// baseline (speedup 1.0000x reference)
#include <cuda_runtime.h>
#include <cstdint>

// BlockMaskGenerator: rasterize 4 random rectangles per batch into a
// 256 x 16384 boolean target mask + complement context mask.
// Harness promotes bool outputs to float32:
//   d_out = [context_mask (256*16384 f32), target_mask (256*16384 f32)]
// Pure write-bandwidth problem: 33.5 MB stores, ~0 reads.

#define BM_BATCH   256
#define BM_NBLK    4
#define BM_H       128
#define BM_W       128
#define BM_SEQ     (BM_H * BM_W)

__global__ __launch_bounds__(512, 2)
void block_mask_kernel(const float* __restrict__ scales_u,
                       const float* __restrict__ rand_top,
                       const float* __restrict__ rand_left,
                       float* __restrict__ out)
{
    __shared__ int s_top[BM_NBLK], s_bot[BM_NBLK], s_left[BM_NBLK], s_right[BM_NBLK];

    const int b   = blockIdx.x;
    const int tid = threadIdx.x;

    if (tid < BM_NBLK) {
        const int i = b * BM_NBLK + tid;
        // scales = 0.15 + u * 0.05  (separate mul then add, f32 rn — match JAX;
        // intrinsics prevent FFMA contraction which would change rounding)
        float scale = __fadd_rn(0.15f, __fmul_rn(scales_u[i], 0.05f));
        // block_areas = int32(scale * H * W)  (pow2 multiplies are exact)
        float areaf = __fmul_rn(__fmul_rn(scale, 128.0f), 128.0f);
        int area = (int)areaf;                       // trunc == astype(int32)
        // block_h = clip(int32(sqrt(area / 0.75)), 1, H)
        int h = (int)__fsqrt_rn(__fdiv_rn((float)area, 0.75f));
        h = min(max(h, 1), BM_H);
        // block_w = clip(int32(area / h), 1, W)
        int w = (int)__fdiv_rn((float)area, (float)h);
        w = min(max(w, 1), BM_W);
        int max_t = max(BM_H - h + 1, 1);
        int max_l = max(BM_W - w + 1, 1);
        int top  = (int)__fmul_rn(rand_top[i],  (float)max_t);
        int left = (int)__fmul_rn(rand_left[i], (float)max_l);
        s_top[tid]   = top;
        s_bot[tid]   = top + h;
        s_left[tid]  = left;
        s_right[tid] = left + w;
    }
    __syncthreads();

    // 512 threads: thread -> (row, 32-col segment). 32 floats per mask per thread.
    const int row   = tid >> 2;
    const int seg   = tid & 3;
    const int cbase = seg * 32;

    // 32-bit column membership mask for this row/segment
    unsigned m = 0u;
#pragma unroll
    for (int j = 0; j < BM_NBLK; j++) {
        bool row_in = (row >= s_top[j]) & (row < s_bot[j]);
        int lo = max(s_left[j]  - cbase, 0);
        int hi = min(s_right[j] - cbase, 32);
        if (row_in && hi > lo) {
            unsigned himask = (hi == 32) ? 0xFFFFFFFFu : ((1u << hi) - 1u);
            unsigned lomask = (1u << lo) - 1u;
            m |= (himask & ~lomask);
        }
    }

    float* ctx = out;
    float* tgt = out + (size_t)BM_BATCH * BM_SEQ;
    const size_t off = (size_t)b * BM_SEQ + (size_t)row * BM_W + cbase;

    const unsigned ONE = 0x3F800000u;  // 1.0f

#pragma unroll
    for (int g = 0; g < 8; g++) {
        unsigned nib = (m >> (4 * g)) & 0xFu;
        uint4 t, c;
        t.x = (nib & 1u) ? ONE : 0u;
        t.y = (nib & 2u) ? ONE : 0u;
        t.z = (nib & 4u) ? ONE : 0u;
        t.w = (nib & 8u) ? ONE : 0u;
        c.x = t.x ^ ONE;
        c.y = t.y ^ ONE;
        c.z = t.z ^ ONE;
        c.w = t.w ^ ONE;
        *reinterpret_cast<uint4*>(tgt + off + 4 * g) = t;
        *reinterpret_cast<uint4*>(ctx + off + 4 * g) = c;
    }
}

extern "C" void kernel_launch(void* const* d_in, const int* in_sizes, int n_in,
                              void* d_out, int out_size)
{
    const float* scales_u  = (const float*)d_in[0];
    const float* rand_top  = (const float*)d_in[1];
    const float* rand_left = (const float*)d_in[2];
    float* out = (float*)d_out;

    block_mask_kernel<<<BM_BATCH, 512>>>(scales_u, rand_top, rand_left, out);
}

// round 4
// speedup vs baseline: 1.1532x; 1.1532x over previous
#include <cuda_runtime.h>
#include <cstdint>

// BlockMaskGenerator: rasterize 4 random rectangles per batch into a
// 256 x 16384 boolean target mask + complement context mask (bool -> f32).
//   d_out = [context_mask (256*16384 f32), target_mask (256*16384 f32)]
// 33.5 MB pure stores; output fits in L2, so floor is the LTS cap (~2.7us).
// R3 profile: occupancy/grid-shape bound (occ 39%, issue 5%). Fix: 2048 CTAs
// x 256 threads, 4 STG.128 per thread.

#define BM_BATCH   256
#define BM_NBLK    4
#define BM_H       128
#define BM_W       128
#define BM_SEQ     (BM_H * BM_W)
#define ROWS_PER_CTA 16

__global__ __launch_bounds__(256, 8)
void block_mask_kernel(const float* __restrict__ scales_u,
                       const float* __restrict__ rand_top,
                       const float* __restrict__ rand_left,
                       float* __restrict__ out)
{
    __shared__ int s_top[BM_NBLK], s_bot[BM_NBLK], s_left[BM_NBLK], s_right[BM_NBLK];

    const int bid = blockIdx.x;
    const int b   = bid >> 3;              // batch
    const int r0  = (bid & 7) * ROWS_PER_CTA;
    const int tid = threadIdx.x;

    if (tid < BM_NBLK) {
        const int i = b * BM_NBLK + tid;
        // scales = 0.15 + u * 0.05  (separate mul then add, f32 rn — match JAX;
        // intrinsics prevent FFMA contraction which would change rounding)
        float scale = __fadd_rn(0.15f, __fmul_rn(scales_u[i], 0.05f));
        // block_areas = int32(scale * H * W)  (pow2 multiplies are exact)
        float areaf = __fmul_rn(__fmul_rn(scale, 128.0f), 128.0f);
        int area = (int)areaf;                       // trunc == astype(int32)
        // block_h = clip(int32(sqrt(area / 0.75)), 1, H)
        int h = (int)__fsqrt_rn(__fdiv_rn((float)area, 0.75f));
        h = min(max(h, 1), BM_H);
        // block_w = clip(int32(area / h), 1, W)
        int w = (int)__fdiv_rn((float)area, (float)h);
        w = min(max(w, 1), BM_W);
        int max_t = max(BM_H - h + 1, 1);
        int max_l = max(BM_W - w + 1, 1);
        int top  = (int)__fmul_rn(rand_top[i],  (float)max_t);
        int left = (int)__fmul_rn(rand_left[i], (float)max_l);
        s_top[tid]   = top;
        s_bot[tid]   = top + h;
        s_left[tid]  = left;
        s_right[tid] = left + w;
    }
    __syncthreads();

    // 256 threads: thread -> (row within 16, 8-col segment). 8 floats per mask.
    const int row   = r0 + (tid >> 4);
    const int seg   = tid & 15;
    const int cbase = seg * 8;

    // 8-bit column membership mask for this row/segment
    unsigned m = 0u;
#pragma unroll
    for (int j = 0; j < BM_NBLK; j++) {
        bool row_in = (row >= s_top[j]) & (row < s_bot[j]);
        int lo = max(s_left[j]  - cbase, 0);
        int hi = min(s_right[j] - cbase, 8);
        if (row_in && hi > lo) {
            unsigned himask = (1u << hi) - 1u;   // hi <= 8, no overflow
            unsigned lomask = (1u << lo) - 1u;
            m |= (himask & ~lomask);
        }
    }

    float* ctx = out;
    float* tgt = out + (size_t)BM_BATCH * BM_SEQ;
    const size_t off = (size_t)b * BM_SEQ + (size_t)row * BM_W + cbase;

    const unsigned ONE = 0x3F800000u;  // 1.0f

    uint4 t0, t1, c0, c1;
    t0.x = (m & 1u)   ? ONE : 0u;
    t0.y = (m & 2u)   ? ONE : 0u;
    t0.z = (m & 4u)   ? ONE : 0u;
    t0.w = (m & 8u)   ? ONE : 0u;
    t1.x = (m & 16u)  ? ONE : 0u;
    t1.y = (m & 32u)  ? ONE : 0u;
    t1.z = (m & 64u)  ? ONE : 0u;
    t1.w = (m & 128u) ? ONE : 0u;
    c0.x = t0.x ^ ONE;  c0.y = t0.y ^ ONE;  c0.z = t0.z ^ ONE;  c0.w = t0.w ^ ONE;
    c1.x = t1.x ^ ONE;  c1.y = t1.y ^ ONE;  c1.z = t1.z ^ ONE;  c1.w = t1.w ^ ONE;

    *reinterpret_cast<uint4*>(tgt + off)     = t0;
    *reinterpret_cast<uint4*>(tgt + off + 4) = t1;
    *reinterpret_cast<uint4*>(ctx + off)     = c0;
    *reinterpret_cast<uint4*>(ctx + off + 4) = c1;
}

extern "C" void kernel_launch(void* const* d_in, const int* in_sizes, int n_in,
                              void* d_out, int out_size)
{
    const float* scales_u  = (const float*)d_in[0];
    const float* rand_top  = (const float*)d_in[1];
    const float* rand_left = (const float*)d_in[2];
    float* out = (float*)d_out;

    block_mask_kernel<<<BM_BATCH * 8, 256>>>(scales_u, rand_top, rand_left, out);
}